// round 16
// baseline (speedup 1.0000x reference)
#include <cuda_runtime.h>
#include <cuda_fp16.h>
#include <math.h>
#include <stdint.h>

// Problem: inputs (64,64,64,64) fp32, codebook (1024,64) fp32
#define N_ROWS   262144
#define DIM      64
#define KCODES   1024
#define ND_ELEMS (N_ROWS * DIM)

#define THREADS  256              // 8 warps, each owns m16 rows
#define M_CTA    128
#define CTAS     (N_ROWS / M_CTA) // 2048
#define CHUNK_N  128
#define NCHUNKS  (KCODES / CHUNK_N)

// smem bytes: B_hi [buf2][16KB] = 32KB, cnorm 4KB, red 64B
#define SMB_B      0
#define SMB_CN     32768
#define SMB_RED    36864
#define SMEM_BYTES 36928

// ---------------------------------------------------------------------------
__device__ float        g_cnorm[KCODES];
__device__ unsigned int g_counts[KCODES];
__device__ double       g_sse;
__device__ __align__(16) __half g_cbh[KCODES * DIM];   // fp16 hi of codebook

// ---------------------------------------------------------------------------
__device__ __forceinline__ uint32_t smem_u32(const void* p) {
    uint32_t a;
    asm("{ .reg .u64 t; cvta.to.shared.u64 t, %1; cvt.u32.u64 %0, t; }" : "=r"(a) : "l"(p));
    return a;
}
__device__ __forceinline__ void cp_async16(uint32_t dst, const void* src) {
    asm volatile("cp.async.cg.shared.global [%0], [%1], 16;" :: "r"(dst), "l"(src));
}
#define CP_COMMIT() asm volatile("cp.async.commit_group;" ::: "memory")

#define LDM4(r0, r1, r2, r3, addr) \
    asm volatile("ldmatrix.sync.aligned.m8n8.x4.shared.b16 {%0,%1,%2,%3}, [%4];" \
        : "=r"(r0), "=r"(r1), "=r"(r2), "=r"(r3) : "r"(addr))

__device__ __forceinline__ void mma_f16(float d[4], const uint32_t a[4],
                                        uint32_t b0, uint32_t b1) {
    asm volatile(
        "mma.sync.aligned.m16n8k16.row.col.f32.f16.f16.f32 "
        "{%0,%1,%2,%3},{%4,%5,%6,%7},{%8,%9},{%0,%1,%2,%3};"
        : "+f"(d[0]), "+f"(d[1]), "+f"(d[2]), "+f"(d[3])
        : "r"(a[0]), "r"(a[1]), "r"(a[2]), "r"(a[3]), "r"(b0), "r"(b1));
}

// fp16 hi of a float2, packed as half2 word
__device__ __forceinline__ uint32_t hi2(float2 v) {
    __half2 hh = __halves2half2(__float2half_rn(v.x), __float2half_rn(v.y));
    return *reinterpret_cast<uint32_t*>(&hh);
}

// embed code index into low 10 mantissa bits (single LOP3)
__device__ __forceinline__ float emb(float d, int code) {
    return __uint_as_float((__float_as_uint(d) & 0xFFFFFC00u) | (uint32_t)code);
}
// branch-free float best-2 (3 FMNMX)
__device__ __forceinline__ void fupd2(float& b1, float& b2, float k) {
    float mn = fminf(k, b1);
    b2 = fminf(fmaxf(k, b1), b2);
    b1 = mn;
}

// (a,ia) < (b,ib) with index tie-break (exact-refine comparison)
__device__ __forceinline__ bool dless(float a, int ia, float b, int ib) {
    return a < b || (a == b && ia < ib);
}

// ---------------------------------------------------------------------------
// Kernel 1: fp16 hi of codebook + cnorm + zero accumulators
// ---------------------------------------------------------------------------
__global__ void vq_split(const float* __restrict__ codebook) {
    __shared__ float s_part[32];
    const int base = blockIdx.x * 1024;
    const int idx  = base + threadIdx.x;
    float x  = codebook[idx];
    g_cbh[idx] = __float2half_rn(x);

    float p = x * x;
    #pragma unroll
    for (int o = 16; o > 0; o >>= 1) p += __shfl_down_sync(0xffffffffu, p, o);
    const int w = threadIdx.x >> 5;
    if ((threadIdx.x & 31) == 0) s_part[w] = p;
    __syncthreads();
    if (threadIdx.x < 16) {
        g_cnorm[base / 64 + threadIdx.x] = s_part[2 * threadIdx.x] + s_part[2 * threadIdx.x + 1];
        g_counts[blockIdx.x * 16 + threadIdx.x] = 0u;
    }
    if (idx == 0) g_sse = 0.0;
}

// ---------------------------------------------------------------------------
// Kernel 2: 1-combo fp16 screening, keyed per-lane best-2, exact fp32
//           refine of all 8 per-row candidates. 256 thr, 5 CTAs/SM.
// ---------------------------------------------------------------------------
__global__ __launch_bounds__(THREADS, 5)
void vq_tc(const float* __restrict__ inputs,
           const float* __restrict__ codebook,
           float* __restrict__ out_q,
           float* __restrict__ out_tok) {
    extern __shared__ float smf[];
    const uint32_t smb = smem_u32(smf);
    float* s_cn = (float*)((char*)smf + SMB_CN);
    float* s_rd = (float*)((char*)smf + SMB_RED);

    const int tid  = threadIdx.x;
    const int w    = tid >> 5;         // 0..7
    const int lane = tid & 31;
    const int grp  = lane >> 2;        // m-row within tile (0..7)
    const int qt   = lane & 3;         // k-thread in quad

    const int r0 = blockIdx.x * M_CTA + w * 16 + grp;
    const int r1 = r0 + 8;

    // ---- A_hi fragments in registers (16 regs) ----
    uint32_t ahi[4][4];
    {
        const float* x0 = inputs + (size_t)r0 * DIM;
        const float* x1 = inputs + (size_t)r1 * DIM;
        #pragma unroll
        for (int s = 0; s < 4; s++) {
            const int k0 = 16 * s + 2 * qt;
            ahi[s][0] = hi2(*(const float2*)(x0 + k0));
            ahi[s][1] = hi2(*(const float2*)(x1 + k0));
            ahi[s][2] = hi2(*(const float2*)(x0 + k0 + 8));
            ahi[s][3] = hi2(*(const float2*)(x1 + k0 + 8));
        }
    }

    // ---- cnorm to smem ----
    #pragma unroll
    for (int i = tid; i < KCODES; i += THREADS) s_cn[i] = g_cnorm[i];

    // ---- B chunk loader: hi plane only, 4 x cp.async(16B) per thread ----
    const int lnl = tid >> 1;          // code within chunk (0..127)
    const int lh  = tid & 1;           // half -> k-units 4h..4h+3
    #define LOAD_CHUNK(c, buf) do {                                                  \
        const __half* _src = g_cbh + ((size_t)((c) * CHUNK_N + lnl)) * DIM + lh * 32;\
        uint32_t _dst = smb + SMB_B + (uint32_t)((buf) * 16384 + lnl * 128);         \
        _Pragma("unroll")                                                            \
        for (int _j = 0; _j < 4; _j++) {                                             \
            int _u = lh * 4 + _j;                                                    \
            cp_async16(_dst + ((_u ^ (lnl & 7)) * 16), _src + _j * 8);               \
        }                                                                            \
        CP_COMMIT();                                                                 \
    } while (0)

    LOAD_CHUNK(0, 0);

    // ldmatrix per-lane address components
    const int nloc = ((lane >> 4) & 1) * 8 + (lane & 7);  // B row within 16-pair
    const int ubit = (lane >> 3) & 1;                     // k-unit parity
    const int s7   = lane & 7;                            // swizzle key

    // per-lane best-2 keyed floats (index in low 10 mantissa bits), per m-row
    float b1[2] = { 3.402823466e38f, 3.402823466e38f };
    float b2[2] = { 3.402823466e38f, 3.402823466e38f };

    for (int c = 0; c < NCHUNKS; c++) {
        if (c + 1 < NCHUNKS) {
            LOAD_CHUNK(c + 1, (c + 1) & 1);
            asm volatile("cp.async.wait_group 1;" ::: "memory");
        } else {
            asm volatile("cp.async.wait_group 0;" ::: "memory");
        }
        __syncthreads();

        const uint32_t rowH = smb + SMB_B + (uint32_t)((c & 1) * 16384) + nloc * 128;

        #pragma unroll
        for (int t = 0; t < 8; t++) {           // 16 codes per tile
            float acc0[4] = {0.f, 0.f, 0.f, 0.f};
            float acc1[4] = {0.f, 0.f, 0.f, 0.f};
            const uint32_t rb = rowH + t * 2048;

            #pragma unroll
            for (int s = 0; s < 4; s++) {       // k16 steps
                const uint32_t uoff = (uint32_t)(((2 * s + ubit) ^ s7) * 16);
                uint32_t a0, a1, a2, a3;
                LDM4(a0, a1, a2, a3, rb + uoff);
                mma_f16(acc0, ahi[s], a0, a1);  // codes g..g+7
                mma_f16(acc1, ahi[s], a2, a3);  // codes g+8..g+15
            }

            // epilogue: dist = |c|^2 - 2*dot (FFMA), key = dist w/ index
            // embedded in low mantissa bits (LOP3), best-2 via FMNMX
            const int g = c * CHUNK_N + t * 16 + 2 * qt;
            const float c0 = s_cn[g],     c1 = s_cn[g + 1];
            const float c8 = s_cn[g + 8], c9 = s_cn[g + 9];
            // row r0 (C frag elems 0,1)
            fupd2(b1[0], b2[0], emb(fmaf(-2.f, acc0[0], c0), g));
            fupd2(b1[0], b2[0], emb(fmaf(-2.f, acc0[1], c1), g + 1));
            fupd2(b1[0], b2[0], emb(fmaf(-2.f, acc1[0], c8), g + 8));
            fupd2(b1[0], b2[0], emb(fmaf(-2.f, acc1[1], c9), g + 9));
            // row r1 (C frag elems 2,3)
            fupd2(b1[1], b2[1], emb(fmaf(-2.f, acc0[2], c0), g));
            fupd2(b1[1], b2[1], emb(fmaf(-2.f, acc0[3], c1), g + 1));
            fupd2(b1[1], b2[1], emb(fmaf(-2.f, acc1[2], c8), g + 8));
            fupd2(b1[1], b2[1], emb(fmaf(-2.f, acc1[3], c9), g + 9));
        }
        __syncthreads();
    }

    // ---- per-lane exact fp32 refine of BOTH lane candidates, then
    //      cross-lane exact min (covers 8 candidates per row) ----
    float sse = 0.f;
    #pragma unroll
    for (int mt = 0; mt < 2; mt++) {
        const int row = mt ? r1 : r0;
        const float* xr = inputs + (size_t)row * DIM;

        float eb = 3.402823466e38f;
        int   ib = 0;
        const int cand[2] = { (int)(__float_as_uint(b1[mt]) & 1023u),
                              (int)(__float_as_uint(b2[mt]) & 1023u) };
        #pragma unroll
        for (int k = 0; k < 2; k++) {
            const float* cp = codebook + (size_t)cand[k] * DIM;
            float s0 = 0.f, s1 = 0.f, s2 = 0.f, s3 = 0.f;
            #pragma unroll
            for (int j = 0; j < 16; j++) {
                const float4 xv = *(const float4*)(xr + 4 * j);
                const float4 cv = *(const float4*)(cp + 4 * j);
                s0 = fmaf(xv.x, cv.x, s0);
                s1 = fmaf(xv.y, cv.y, s1);
                s2 = fmaf(xv.z, cv.z, s2);
                s3 = fmaf(xv.w, cv.w, s3);
            }
            const float e = s_cn[cand[k]] - 2.0f * ((s0 + s1) + (s2 + s3));
            if (dless(e, cand[k], eb, ib)) { eb = e; ib = cand[k]; }
        }

        // cross-lane min over the 4 quad lanes (all lanes execute)
        #pragma unroll
        for (int off = 1; off <= 2; off <<= 1) {
            float ex = __shfl_xor_sync(0xffffffffu, eb, off);
            int   jx = __shfl_xor_sync(0xffffffffu, ib, off);
            if (dless(ex, jx, eb, ib)) { eb = ex; ib = jx; }
        }
        const int sel = ib;

        const float4* cq  = (const float4*)(codebook + (size_t)sel * DIM) + qt * 4;
        const float4* xin = (const float4*)(xr) + qt * 4;
        float4* oq = (float4*)(out_q + (size_t)row * DIM) + qt * 4;
        #pragma unroll
        for (int g = 0; g < 4; g++) {
            float4 q = cq[g], x = xin[g];
            float dx = q.x - x.x, dy = q.y - x.y, dz = q.z - x.z, dw = q.w - x.w;
            sse += dx * dx + dy * dy + dz * dz + dw * dw;
            oq[g] = q;
        }
        if (qt == 0) {
            out_tok[row] = (float)sel;
            atomicAdd(&g_counts[sel], 1u);
        }
    }

    // ---- SSE block reduce ----
    #pragma unroll
    for (int o = 16; o > 0; o >>= 1) sse += __shfl_down_sync(0xffffffffu, sse, o);
    if (lane == 0) s_rd[w] = sse;
    __syncthreads();
    if (tid == 0) {
        float s = 0.f;
        #pragma unroll
        for (int i = 0; i < THREADS / 32; i++) s += s_rd[i];
        atomicAdd(&g_sse, (double)s);
    }
}

// ---------------------------------------------------------------------------
// Kernel 3: perplexity + scalar losses
// ---------------------------------------------------------------------------
__global__ void vq_finalize(float* __restrict__ out_scalars) {
    __shared__ double s_red[32];
    const int j = threadIdx.x;
    double p    = (double)g_counts[j] / (double)N_ROWS;
    double term = p * log(p + 1e-10);
    #pragma unroll
    for (int o = 16; o > 0; o >>= 1)
        term += __shfl_down_sync(0xffffffffu, term, o);
    const int lane = j & 31, wid = j >> 5;
    if (lane == 0) s_red[wid] = term;
    __syncthreads();
    if (j == 0) {
        double tot = 0.0;
        #pragma unroll
        for (int w = 0; w < 32; w++) tot += s_red[w];
        double perp = exp(-tot);
        double L = g_sse / (double)ND_ELEMS;
        out_scalars[0] = (float)(1.25 * L);
        out_scalars[1] = (float)(0.25 * L);
        out_scalars[2] = (float)L;
        out_scalars[3] = (float)perp;
    }
}

// ---------------------------------------------------------------------------
extern "C" void kernel_launch(void* const* d_in, const int* in_sizes, int n_in,
                              void* d_out, int out_size) {
    const float* inputs   = (const float*)d_in[0];
    const float* codebook = (const float*)d_in[1];
    float* out = (float*)d_out;

    float* out_q       = out;
    float* out_tok     = out + ND_ELEMS;
    float* out_scalars = out + ND_ELEMS + N_ROWS;

    static int configured = 0;
    if (!configured) {
        cudaFuncSetAttribute(vq_tc, cudaFuncAttributeMaxDynamicSharedMemorySize, SMEM_BYTES);
        configured = 1;
    }

    vq_split<<<KCODES * DIM / 1024, 1024>>>(codebook);
    vq_tc<<<CTAS, THREADS, SMEM_BYTES>>>(inputs, codebook, out_q, out_tok);
    vq_finalize<<<1, 1024>>>(out_scalars);
}

// round 17
// speedup vs baseline: 1.3857x; 1.3857x over previous
#include <cuda_runtime.h>
#include <cuda_fp16.h>
#include <math.h>
#include <stdint.h>

// Problem: inputs (64,64,64,64) fp32, codebook (1024,64) fp32
#define N_ROWS   262144
#define DIM      64
#define KCODES   1024
#define ND_ELEMS (N_ROWS * DIM)

#define THREADS  256              // 8 warps, each owns m32 rows (2 x m16)
#define M_CTA    256
#define CTAS     (N_ROWS / M_CTA) // 1024
#define CHUNK_N  128
#define NCHUNKS  (KCODES / CHUNK_N)

// smem bytes: B_hi [buf2][16KB] = 32KB, cnorm 4KB, red 64B
#define SMB_B      0
#define SMB_CN     32768
#define SMB_RED    36864
#define SMEM_BYTES 36928

// ---------------------------------------------------------------------------
__device__ float        g_cnorm[KCODES];
__device__ unsigned int g_counts[KCODES];
__device__ double       g_sse;
__device__ __align__(16) __half g_cbh[KCODES * DIM];   // fp16 hi of codebook

// ---------------------------------------------------------------------------
__device__ __forceinline__ uint32_t smem_u32(const void* p) {
    uint32_t a;
    asm("{ .reg .u64 t; cvta.to.shared.u64 t, %1; cvt.u32.u64 %0, t; }" : "=r"(a) : "l"(p));
    return a;
}
__device__ __forceinline__ void cp_async16(uint32_t dst, const void* src) {
    asm volatile("cp.async.cg.shared.global [%0], [%1], 16;" :: "r"(dst), "l"(src));
}
#define CP_COMMIT() asm volatile("cp.async.commit_group;" ::: "memory")

#define LDM4(r0, r1, r2, r3, addr) \
    asm volatile("ldmatrix.sync.aligned.m8n8.x4.shared.b16 {%0,%1,%2,%3}, [%4];" \
        : "=r"(r0), "=r"(r1), "=r"(r2), "=r"(r3) : "r"(addr))

__device__ __forceinline__ void mma_f16(float d[4], const uint32_t a[4],
                                        uint32_t b0, uint32_t b1) {
    asm volatile(
        "mma.sync.aligned.m16n8k16.row.col.f32.f16.f16.f32 "
        "{%0,%1,%2,%3},{%4,%5,%6,%7},{%8,%9},{%0,%1,%2,%3};"
        : "+f"(d[0]), "+f"(d[1]), "+f"(d[2]), "+f"(d[3])
        : "r"(a[0]), "r"(a[1]), "r"(a[2]), "r"(a[3]), "r"(b0), "r"(b1));
}

// fp16 hi of a float2, packed as half2 word
__device__ __forceinline__ uint32_t hi2(float2 v) {
    __half2 hh = __halves2half2(__float2half_rn(v.x), __float2half_rn(v.y));
    return *reinterpret_cast<uint32_t*>(&hh);
}

// embed code index into low 10 mantissa bits (single LOP3)
__device__ __forceinline__ float emb(float d, int code) {
    return __uint_as_float((__float_as_uint(d) & 0xFFFFFC00u) | (uint32_t)code);
}
// branch-free float best-2 (3 FMNMX)
__device__ __forceinline__ void fupd2(float& b1, float& b2, float k) {
    float mn = fminf(k, b1);
    b2 = fminf(fmaxf(k, b1), b2);
    b1 = mn;
}

// (a,ia) < (b,ib) with index tie-break (exact-refine comparison)
__device__ __forceinline__ bool dless(float a, int ia, float b, int ib) {
    return a < b || (a == b && ia < ib);
}

// ---------------------------------------------------------------------------
// Kernel 1: fp16 hi of codebook + cnorm + zero accumulators
// ---------------------------------------------------------------------------
__global__ void vq_split(const float* __restrict__ codebook) {
    __shared__ float s_part[32];
    const int base = blockIdx.x * 1024;
    const int idx  = base + threadIdx.x;
    float x  = codebook[idx];
    g_cbh[idx] = __float2half_rn(x);

    float p = x * x;
    #pragma unroll
    for (int o = 16; o > 0; o >>= 1) p += __shfl_down_sync(0xffffffffu, p, o);
    const int w = threadIdx.x >> 5;
    if ((threadIdx.x & 31) == 0) s_part[w] = p;
    __syncthreads();
    if (threadIdx.x < 16) {
        g_cnorm[base / 64 + threadIdx.x] = s_part[2 * threadIdx.x] + s_part[2 * threadIdx.x + 1];
        g_counts[blockIdx.x * 16 + threadIdx.x] = 0u;
    }
    if (idx == 0) g_sse = 0.0;
}

// ---------------------------------------------------------------------------
// Kernel 2: 1-combo fp16 screening, m32 rows/warp (B fragment reuse x2),
//           keyed per-lane best-2, exact fp32 refine. 256 thr, 3 CTAs/SM.
// ---------------------------------------------------------------------------
__global__ __launch_bounds__(THREADS, 3)
void vq_tc(const float* __restrict__ inputs,
           const float* __restrict__ codebook,
           float* __restrict__ out_q,
           float* __restrict__ out_tok) {
    extern __shared__ float smf[];
    const uint32_t smb = smem_u32(smf);
    float* s_cn = (float*)((char*)smf + SMB_CN);
    float* s_rd = (float*)((char*)smf + SMB_RED);

    const int tid  = threadIdx.x;
    const int w    = tid >> 5;         // 0..7
    const int lane = tid & 31;
    const int grp  = lane >> 2;        // m-row within m16 group (0..7)
    const int qt   = lane & 3;         // k-thread in quad

    // warp owns rows rbase + {grp, grp+8, grp+16, grp+24}
    const int rbase = blockIdx.x * M_CTA + w * 32 + grp;

    // ---- A_hi fragments: two m16 groups (32 regs) ----
    uint32_t ahiA[4][4], ahiB[4][4];   // group A rows {grp,grp+8}, B {+16,+24}
    {
        const float* x0 = inputs + (size_t)(rbase)      * DIM;
        const float* x1 = inputs + (size_t)(rbase + 8)  * DIM;
        const float* x2 = inputs + (size_t)(rbase + 16) * DIM;
        const float* x3 = inputs + (size_t)(rbase + 24) * DIM;
        #pragma unroll
        for (int s = 0; s < 4; s++) {
            const int k0 = 16 * s + 2 * qt;
            ahiA[s][0] = hi2(*(const float2*)(x0 + k0));
            ahiA[s][1] = hi2(*(const float2*)(x1 + k0));
            ahiA[s][2] = hi2(*(const float2*)(x0 + k0 + 8));
            ahiA[s][3] = hi2(*(const float2*)(x1 + k0 + 8));
            ahiB[s][0] = hi2(*(const float2*)(x2 + k0));
            ahiB[s][1] = hi2(*(const float2*)(x3 + k0));
            ahiB[s][2] = hi2(*(const float2*)(x2 + k0 + 8));
            ahiB[s][3] = hi2(*(const float2*)(x3 + k0 + 8));
        }
    }

    // ---- cnorm to smem ----
    #pragma unroll
    for (int i = tid; i < KCODES; i += THREADS) s_cn[i] = g_cnorm[i];

    // ---- B chunk loader: hi plane only, 4 x cp.async(16B) per thread ----
    const int lnl = tid >> 1;          // code within chunk (0..127)
    const int lh  = tid & 1;           // half -> k-units 4h..4h+3
    #define LOAD_CHUNK(c, buf) do {                                                  \
        const __half* _src = g_cbh + ((size_t)((c) * CHUNK_N + lnl)) * DIM + lh * 32;\
        uint32_t _dst = smb + SMB_B + (uint32_t)((buf) * 16384 + lnl * 128);         \
        _Pragma("unroll")                                                            \
        for (int _j = 0; _j < 4; _j++) {                                             \
            int _u = lh * 4 + _j;                                                    \
            cp_async16(_dst + ((_u ^ (lnl & 7)) * 16), _src + _j * 8);               \
        }                                                                            \
        CP_COMMIT();                                                                 \
    } while (0)

    LOAD_CHUNK(0, 0);

    // ldmatrix per-lane address components
    const int nloc = ((lane >> 4) & 1) * 8 + (lane & 7);  // B row within 16-pair
    const int ubit = (lane >> 3) & 1;                     // k-unit parity
    const int s7   = lane & 7;                            // swizzle key

    // per-lane best-2 keyed floats, per m-row (4 rows per thread)
    float b1[4] = { 3.402823466e38f, 3.402823466e38f,
                    3.402823466e38f, 3.402823466e38f };
    float b2[4] = { 3.402823466e38f, 3.402823466e38f,
                    3.402823466e38f, 3.402823466e38f };

    for (int c = 0; c < NCHUNKS; c++) {
        if (c + 1 < NCHUNKS) {
            LOAD_CHUNK(c + 1, (c + 1) & 1);
            asm volatile("cp.async.wait_group 1;" ::: "memory");
        } else {
            asm volatile("cp.async.wait_group 0;" ::: "memory");
        }
        __syncthreads();

        const uint32_t rowH = smb + SMB_B + (uint32_t)((c & 1) * 16384) + nloc * 128;

        #pragma unroll
        for (int t = 0; t < 8; t++) {           // 16 codes per tile
            float acc0[4] = {0.f, 0.f, 0.f, 0.f};   // grpA, codes g..g+7
            float acc1[4] = {0.f, 0.f, 0.f, 0.f};   // grpA, codes g+8..g+15
            float acc2[4] = {0.f, 0.f, 0.f, 0.f};   // grpB, codes g..g+7
            float acc3[4] = {0.f, 0.f, 0.f, 0.f};   // grpB, codes g+8..g+15
            const uint32_t rb = rowH + t * 2048;

            #pragma unroll
            for (int s = 0; s < 4; s++) {       // k16 steps
                const uint32_t uoff = (uint32_t)(((2 * s + ubit) ^ s7) * 16);
                uint32_t f0, f1, f2, f3;
                LDM4(f0, f1, f2, f3, rb + uoff);
                mma_f16(acc0, ahiA[s], f0, f1);
                mma_f16(acc1, ahiA[s], f2, f3);
                mma_f16(acc2, ahiB[s], f0, f1);
                mma_f16(acc3, ahiB[s], f2, f3);
            }

            // epilogue: keyed distances, best-2 per row
            const int g = c * CHUNK_N + t * 16 + 2 * qt;
            const float c0 = s_cn[g],     c1 = s_cn[g + 1];
            const float c8 = s_cn[g + 8], c9 = s_cn[g + 9];
            // group A: rows rbase (elems 0,1), rbase+8 (elems 2,3)
            fupd2(b1[0], b2[0], emb(fmaf(-2.f, acc0[0], c0), g));
            fupd2(b1[0], b2[0], emb(fmaf(-2.f, acc0[1], c1), g + 1));
            fupd2(b1[0], b2[0], emb(fmaf(-2.f, acc1[0], c8), g + 8));
            fupd2(b1[0], b2[0], emb(fmaf(-2.f, acc1[1], c9), g + 9));
            fupd2(b1[1], b2[1], emb(fmaf(-2.f, acc0[2], c0), g));
            fupd2(b1[1], b2[1], emb(fmaf(-2.f, acc0[3], c1), g + 1));
            fupd2(b1[1], b2[1], emb(fmaf(-2.f, acc1[2], c8), g + 8));
            fupd2(b1[1], b2[1], emb(fmaf(-2.f, acc1[3], c9), g + 9));
            // group B: rows rbase+16 (elems 0,1), rbase+24 (elems 2,3)
            fupd2(b1[2], b2[2], emb(fmaf(-2.f, acc2[0], c0), g));
            fupd2(b1[2], b2[2], emb(fmaf(-2.f, acc2[1], c1), g + 1));
            fupd2(b1[2], b2[2], emb(fmaf(-2.f, acc3[0], c8), g + 8));
            fupd2(b1[2], b2[2], emb(fmaf(-2.f, acc3[1], c9), g + 9));
            fupd2(b1[3], b2[3], emb(fmaf(-2.f, acc2[2], c0), g));
            fupd2(b1[3], b2[3], emb(fmaf(-2.f, acc2[3], c1), g + 1));
            fupd2(b1[3], b2[3], emb(fmaf(-2.f, acc3[2], c8), g + 8));
            fupd2(b1[3], b2[3], emb(fmaf(-2.f, acc3[3], c9), g + 9));
        }
        __syncthreads();
    }

    // ---- per-lane exact fp32 refine of BOTH lane candidates, then
    //      cross-lane exact min (covers 8 candidates per row) ----
    float sse = 0.f;
    #pragma unroll
    for (int mt = 0; mt < 4; mt++) {
        const int row = rbase + mt * 8;
        const float* xr = inputs + (size_t)row * DIM;

        float eb = 3.402823466e38f;
        int   ib = 0;
        const int cand[2] = { (int)(__float_as_uint(b1[mt]) & 1023u),
                              (int)(__float_as_uint(b2[mt]) & 1023u) };
        #pragma unroll
        for (int k = 0; k < 2; k++) {
            const float* cp = codebook + (size_t)cand[k] * DIM;
            float s0 = 0.f, s1 = 0.f, s2 = 0.f, s3 = 0.f;
            #pragma unroll
            for (int j = 0; j < 16; j++) {
                const float4 xv = *(const float4*)(xr + 4 * j);
                const float4 cv = *(const float4*)(cp + 4 * j);
                s0 = fmaf(xv.x, cv.x, s0);
                s1 = fmaf(xv.y, cv.y, s1);
                s2 = fmaf(xv.z, cv.z, s2);
                s3 = fmaf(xv.w, cv.w, s3);
            }
            const float e = s_cn[cand[k]] - 2.0f * ((s0 + s1) + (s2 + s3));
            if (dless(e, cand[k], eb, ib)) { eb = e; ib = cand[k]; }
        }

        // cross-lane min over the 4 quad lanes (all lanes execute)
        #pragma unroll
        for (int off = 1; off <= 2; off <<= 1) {
            float ex = __shfl_xor_sync(0xffffffffu, eb, off);
            int   jx = __shfl_xor_sync(0xffffffffu, ib, off);
            if (dless(ex, jx, eb, ib)) { eb = ex; ib = jx; }
        }
        const int sel = ib;

        const float4* cq  = (const float4*)(codebook + (size_t)sel * DIM) + qt * 4;
        const float4* xin = (const float4*)(xr) + qt * 4;
        float4* oq = (float4*)(out_q + (size_t)row * DIM) + qt * 4;
        #pragma unroll
        for (int g = 0; g < 4; g++) {
            float4 q = cq[g], x = xin[g];
            float dx = q.x - x.x, dy = q.y - x.y, dz = q.z - x.z, dw = q.w - x.w;
            sse += dx * dx + dy * dy + dz * dz + dw * dw;
            oq[g] = q;
        }
        if (qt == 0) {
            out_tok[row] = (float)sel;
            atomicAdd(&g_counts[sel], 1u);
        }
    }

    // ---- SSE block reduce ----
    #pragma unroll
    for (int o = 16; o > 0; o >>= 1) sse += __shfl_down_sync(0xffffffffu, sse, o);
    if (lane == 0) s_rd[w] = sse;
    __syncthreads();
    if (tid == 0) {
        float s = 0.f;
        #pragma unroll
        for (int i = 0; i < THREADS / 32; i++) s += s_rd[i];
        atomicAdd(&g_sse, (double)s);
    }
}

// ---------------------------------------------------------------------------
// Kernel 3: perplexity + scalar losses
// ---------------------------------------------------------------------------
__global__ void vq_finalize(float* __restrict__ out_scalars) {
    __shared__ double s_red[32];
    const int j = threadIdx.x;
    double p    = (double)g_counts[j] / (double)N_ROWS;
    double term = p * log(p + 1e-10);
    #pragma unroll
    for (int o = 16; o > 0; o >>= 1)
        term += __shfl_down_sync(0xffffffffu, term, o);
    const int lane = j & 31, wid = j >> 5;
    if (lane == 0) s_red[wid] = term;
    __syncthreads();
    if (j == 0) {
        double tot = 0.0;
        #pragma unroll
        for (int w = 0; w < 32; w++) tot += s_red[w];
        double perp = exp(-tot);
        double L = g_sse / (double)ND_ELEMS;
        out_scalars[0] = (float)(1.25 * L);
        out_scalars[1] = (float)(0.25 * L);
        out_scalars[2] = (float)L;
        out_scalars[3] = (float)perp;
    }
}

// ---------------------------------------------------------------------------
extern "C" void kernel_launch(void* const* d_in, const int* in_sizes, int n_in,
                              void* d_out, int out_size) {
    const float* inputs   = (const float*)d_in[0];
    const float* codebook = (const float*)d_in[1];
    float* out = (float*)d_out;

    float* out_q       = out;
    float* out_tok     = out + ND_ELEMS;
    float* out_scalars = out + ND_ELEMS + N_ROWS;

    static int configured = 0;
    if (!configured) {
        cudaFuncSetAttribute(vq_tc, cudaFuncAttributeMaxDynamicSharedMemorySize, SMEM_BYTES);
        configured = 1;
    }

    vq_split<<<KCODES * DIM / 1024, 1024>>>(codebook);
    vq_tc<<<CTAS, THREADS, SMEM_BYTES>>>(inputs, codebook, out_q, out_tok);
    vq_finalize<<<1, 1024>>>(out_scalars);
}